// round 12
// baseline (speedup 1.0000x reference)
#include <cuda_runtime.h>
#include <cstdint>

#define N1     2048
#define N2     2048
#define D      64
#define TILE   64
#define SPLITS 16
#define SPAN   (N2 / SPLITS)     // 128 m per block
#define NT     (SPAN / TILE)     // 2 tiles per block
#define NRG    (N1 / 16)         // 128 rowgroups

// Scratch (allocation-free rule: __device__ globals)
__device__ float  g_kpTh[D * N2];          // 0.5*(k@Wk+bk)^T [d][m]
__device__ float4 g_qw4 [(N1 / 2) * D];    // (q_2p/2, q_2p+1/2, w/2, 0)
__device__ float  g_bias;                  // b + sum_d w_d/2
__device__ float  g_accP[SPLITS * N1 * D]; // partial PV accumulators
__device__ float  g_Ssum[SPLITS * N1];     // partial exp-sums
__device__ int    g_cnt [NRG];             // per-rowgroup completion counters

__device__ __forceinline__ float tanh_fast(float x) {
    float y;
    asm("tanh.approx.f32 %0, %1;" : "=f"(y) : "f"(x));
    return y;
}
__device__ __forceinline__ void cp_async16(void* saddr, const void* gptr) {
    uint32_t s = (uint32_t)__cvta_generic_to_shared(saddr);
    asm volatile("cp.async.cg.shared.global [%0], [%1], 16;" :: "r"(s), "l"(gptr));
}
__device__ __forceinline__ void cp_commit() { asm volatile("cp.async.commit_group;"); }
__device__ __forceinline__ void cp_wait0()  { asm volatile("cp.async.wait_group 0;" ::: "memory"); }

// ---------------------------------------------------------------------------
// Prep. Blocks 0..63   (job 0): row-pair x d-quad -> writes g_qw4 directly.
//       Blocks 64..191 (job 1): row x d-quad -> writes g_kpTh (transposed).
// Block 0 also zeroes combine counters; thread (0,0) computes g_bias.
// ---------------------------------------------------------------------------
__global__ void prep_kernel(const float* __restrict__ q,
                            const float* __restrict__ k,
                            const float* __restrict__ Wq, const float* __restrict__ bq,
                            const float* __restrict__ Wk, const float* __restrict__ bk,
                            const float* __restrict__ wvec,
                            const float* __restrict__ bptr) {
    const int tid = threadIdx.x;
    if (blockIdx.x < 64) {
        // job 0: q projection, pair-of-rows per thread
        if (blockIdx.x == 0 && tid < NRG) g_cnt[tid] = 0;
        if (blockIdx.x == 0 && tid == 0) {
            float s = bptr[0];
#pragma unroll
            for (int dd = 0; dd < D; dd++) s += 0.5f * wvec[dd];
            g_bias = s;
        }
        int i  = (blockIdx.x << 8) + tid;     // 0 .. 16383
        int p  = i >> 4;                      // row pair 0..1023
        int d0 = (i & 15) << 2;

        float4 r0a = make_float4(0.f, 0.f, 0.f, 0.f);
        float4 r1a = make_float4(0.f, 0.f, 0.f, 0.f);
#pragma unroll 16
        for (int kk = 0; kk < D; kk++) {
            float  x0 = q[(2 * p) * D + kk];
            float  x1 = q[(2 * p + 1) * D + kk];
            float4 w4 = *(const float4*)&Wq[kk * D + d0];
            r0a.x = fmaf(x0, w4.x, r0a.x);  r1a.x = fmaf(x1, w4.x, r1a.x);
            r0a.y = fmaf(x0, w4.y, r0a.y);  r1a.y = fmaf(x1, w4.y, r1a.y);
            r0a.z = fmaf(x0, w4.z, r0a.z);  r1a.z = fmaf(x1, w4.z, r1a.z);
            r0a.w = fmaf(x0, w4.w, r0a.w);  r1a.w = fmaf(x1, w4.w, r1a.w);
        }
        float4 b4 = *(const float4*)&bq[d0];
        float q0[4] = { 0.5f * (r0a.x + b4.x), 0.5f * (r0a.y + b4.y),
                        0.5f * (r0a.z + b4.z), 0.5f * (r0a.w + b4.w) };
        float q1[4] = { 0.5f * (r1a.x + b4.x), 0.5f * (r1a.y + b4.y),
                        0.5f * (r1a.z + b4.z), 0.5f * (r1a.w + b4.w) };
#pragma unroll
        for (int jj = 0; jj < 4; jj++) {
            int d = d0 + jj;
            g_qw4[p * D + d] = make_float4(q0[jj], q1[jj], 0.5f * wvec[d], 0.f);
        }
    } else {
        // job 1: k projection -> transposed halved
        int i  = ((blockIdx.x - 64) << 8) + tid;   // 0 .. 32767
        int n  = i >> 4;
        int d0 = (i & 15) << 2;

        float4 acc = make_float4(0.f, 0.f, 0.f, 0.f);
#pragma unroll 16
        for (int kk = 0; kk < D; kk++) {
            float  xs = k[n * D + kk];
            float4 w4 = *(const float4*)&Wk[kk * D + d0];
            acc.x = fmaf(xs, w4.x, acc.x);
            acc.y = fmaf(xs, w4.y, acc.y);
            acc.z = fmaf(xs, w4.z, acc.z);
            acc.w = fmaf(xs, w4.w, acc.w);
        }
        float4 b4 = *(const float4*)&bk[d0];
        g_kpTh[(d0 + 0) * N2 + n] = 0.5f * (acc.x + b4.x);
        g_kpTh[(d0 + 1) * N2 + n] = 0.5f * (acc.y + b4.y);
        g_kpTh[(d0 + 2) * N2 + n] = 0.5f * (acc.z + b4.z);
        g_kpTh[(d0 + 3) * N2 + n] = 0.5f * (acc.w + b4.w);
    }
}

// ---------------------------------------------------------------------------
// Main fused kernel. Grid = 2048: (rowgroup 0..127) x (split 0..15).
// Block 256 thr = 8 warps x 2 rows = 16 rows; block does SPAN=128 of N2.
// Software pipeline: PV(t-1) interleaved into score loop of tile t.
// Last-arriving block of each rowgroup combines the 16 partials inline.
// ---------------------------------------------------------------------------
__global__ __launch_bounds__(256, 2)
void attn_kernel(const float* __restrict__ vglob,    // [N2, D] original v
                 float* __restrict__ out,            // [N1, D]
                 float* __restrict__ att_score) {    // [N1, N2]
    extern __shared__ float sm[];
    float*  kb0 = sm;
    float*  kb1 = sm + 4096;
    float*  vbb = sm + 8192;               // 3 x 4096
    float4* qws = (float4*)(sm + 20480);   // [8 warps][64 d]
    float*  psm = sm + 22528;              // [8 warps][64 m][2 rows]

    const int tid   = threadIdx.x;
    const int warp  = tid >> 5;
    const int lane  = tid & 31;
    const int split = blockIdx.x & (SPLITS - 1);
    const int rg    = blockIdx.x >> 4;
    const int n0    = rg * 16;
    const int r0    = n0 + 2 * warp;
    const int r1    = r0 + 1;
    const int mbase = split * SPAN;

    // prologue: one cp.async group = qws table slice + tile 0 (k, v)
    {
        const float4* src = g_qw4 + rg * 512;
        cp_async16(qws + tid,       src + tid);
        cp_async16(qws + tid + 256, src + tid + 256);
        int r = tid >> 4, c = (tid & 15) << 2;
#pragma unroll
        for (int j = 0; j < 4; j++) {
            int rr = r + j * 16;
            cp_async16(kb0 + rr * 64 + c, g_kpTh + rr * N2 + mbase + c);
            cp_async16(vbb + rr * 64 + c, vglob + (mbase + rr) * D + c);
        }
        cp_commit();
    }
    const float bias = g_bias;

    float2 a0 = make_float2(0.f, 0.f);
    float2 a1 = make_float2(0.f, 0.f);
    float  S0 = 0.f, S1 = 0.f;

    float2* sr0 = (float2*)(att_score + (size_t)r0 * N2 + mbase);
    float2* sr1 = (float2*)(att_score + (size_t)r1 * N2 + mbase);
    float*  pw  = psm + warp * 128;

    for (int t = 0; t < NT; t++) {
        cp_wait0();
        __syncthreads();

        const float* kt = (t & 1) ? kb1 : kb0;

        if (t + 1 < NT) {
            float* kn = (t & 1) ? kb0 : kb1;
            float* vn = vbb + ((t + 1) % 3) * 4096;
            int r = tid >> 4, c = (tid & 15) << 2;
            int col0 = mbase + (t + 1) * 64;
#pragma unroll
            for (int j = 0; j < 4; j++) {
                int rr = r + j * 16;
                cp_async16(kn + rr * 64 + c, g_kpTh + rr * N2 + col0 + c);
                cp_async16(vn + rr * 64 + c, vglob + (col0 + rr) * D + c);
            }
            cp_commit();
        }

        float s00 = 0.f, s01 = 0.f, s10 = 0.f, s11 = 0.f;

        if (t == 0) {
#pragma unroll 8
            for (int d = 0; d < D; d++) {
                float4 qw = qws[warp * 64 + d];
                float2 kk = ((const float2*)(kt + d * 64))[lane];
                float t00 = tanh_fast(qw.x + kk.x);
                float t01 = tanh_fast(qw.x + kk.y);
                float t10 = tanh_fast(qw.y + kk.x);
                float t11 = tanh_fast(qw.y + kk.y);
                s00 = fmaf(qw.z, t00, s00);
                s01 = fmaf(qw.z, t01, s01);
                s10 = fmaf(qw.z, t10, s10);
                s11 = fmaf(qw.z, t11, s11);
            }
        } else {
            const float* vprev = vbb + ((t - 1) % 3) * 4096;
#pragma unroll 8
            for (int d = 0; d < D; d++) {
                float4 qw = qws[warp * 64 + d];
                float2 kk = ((const float2*)(kt + d * 64))[lane];
                float t00 = tanh_fast(qw.x + kk.x);
                float t01 = tanh_fast(qw.x + kk.y);
                float t10 = tanh_fast(qw.y + kk.x);
                float t11 = tanh_fast(qw.y + kk.y);
                s00 = fmaf(qw.z, t00, s00);
                s01 = fmaf(qw.z, t01, s01);
                s10 = fmaf(qw.z, t10, s10);
                s11 = fmaf(qw.z, t11, s11);
                float2 pp = ((const float2*)pw)[d];
                float2 vv = ((const float2*)(vprev + d * 64))[lane];
                a0.x = fmaf(pp.x, vv.x, a0.x);
                a0.y = fmaf(pp.x, vv.y, a0.y);
                a1.x = fmaf(pp.y, vv.x, a1.x);
                a1.y = fmaf(pp.y, vv.y, a1.y);
            }
        }
        s00 += bias; s01 += bias; s10 += bias; s11 += bias;
        sr0[t * 32 + lane] = make_float2(s00, s01);
        sr1[t * 32 + lane] = make_float2(s10, s11);

        float p00 = __expf(s00), p01 = __expf(s01);
        float p10 = __expf(s10), p11 = __expf(s11);
        S0 += p00 + p01;
        S1 += p10 + p11;

        __syncwarp();
        ((float2*)pw)[2 * lane]     = make_float2(p00, p10);
        ((float2*)pw)[2 * lane + 1] = make_float2(p01, p11);
        __syncwarp();
    }

    // epilogue: PV for last tile
    {
        const float* vlast = vbb + ((NT - 1) % 3) * 4096;
#pragma unroll 8
        for (int m = 0; m < TILE; m++) {
            float2 pp = ((const float2*)pw)[m];
            float2 vv = ((const float2*)(vlast + m * 64))[lane];
            a0.x = fmaf(pp.x, vv.x, a0.x);
            a0.y = fmaf(pp.x, vv.y, a0.y);
            a1.x = fmaf(pp.y, vv.x, a1.x);
            a1.y = fmaf(pp.y, vv.y, a1.y);
        }
    }

#pragma unroll
    for (int off = 16; off; off >>= 1) {
        S0 += __shfl_xor_sync(0xffffffffu, S0, off);
        S1 += __shfl_xor_sync(0xffffffffu, S1, off);
    }

    ((float2*)(g_accP + ((size_t)split * N1 + r0) * D))[lane] = a0;
    ((float2*)(g_accP + ((size_t)split * N1 + r1) * D))[lane] = a1;
    if (lane == 0) {
        g_Ssum[split * N1 + r0] = S0;
        g_Ssum[split * N1 + r1] = S1;
    }

    // ---- inline combine: last-arriving block of this rowgroup ----
    __threadfence();
    __shared__ int is_last;
    if (tid == 0) {
        int old = atomicAdd(&g_cnt[rg], 1);
        is_last = (old == SPLITS - 1);
    }
    __syncthreads();
    if (is_last) {
        // 256 threads = 16 rows x 16 d-quads
        int n  = n0 + (tid >> 4);
        int d0 = (tid & 15) << 2;
        float4 a = make_float4(0.f, 0.f, 0.f, 0.f);
        float  S = 0.f;
#pragma unroll
        for (int s = 0; s < SPLITS; s++) {
            float4 p = __ldcg((const float4*)&g_accP[((size_t)s * N1 + n) * D + d0]);
            a.x += p.x; a.y += p.y; a.z += p.z; a.w += p.w;
            S += __ldcg(&g_Ssum[s * N1 + n]);
        }
        float r = __fdividef(1.f, S);
        *(float4*)&out[(size_t)n * D + d0] =
            make_float4(a.x * r, a.y * r, a.z * r, a.w * r);
    }
}

// ---------------------------------------------------------------------------
extern "C" void kernel_launch(void* const* d_in, const int* in_sizes, int n_in,
                              void* d_out, int out_size) {
    const float* q  = (const float*)d_in[0];
    const float* k  = (const float*)d_in[1];
    const float* v  = (const float*)d_in[2];
    const float* Wq = (const float*)d_in[3];
    const float* bq = (const float*)d_in[4];
    const float* Wk = (const float*)d_in[5];
    const float* bk = (const float*)d_in[6];
    const float* w  = (const float*)d_in[7];
    const float* b  = (const float*)d_in[8];

    float* out       = (float*)d_out;          // [N1, D] first
    float* att_score = out + N1 * D;           // then [N1, N2]

    const int SMEM_BYTES = (5 * 4096 + 2048 + 1024) * (int)sizeof(float);   // 94208
    cudaFuncSetAttribute(attn_kernel, cudaFuncAttributeMaxDynamicSharedMemorySize,
                         SMEM_BYTES);

    prep_kernel<<<192, 256>>>(q, k, Wq, bq, Wk, bk, w, b);
    attn_kernel<<<NRG * SPLITS, 256, SMEM_BYTES>>>(v, out, att_score);
}

// round 13
// speedup vs baseline: 1.0932x; 1.0932x over previous
#include <cuda_runtime.h>
#include <cstdint>

#define N1     2048
#define N2     2048
#define D      64
#define TILE   64
#define SPLITS 8
#define SPAN   (N2 / SPLITS)     // 256 m per block
#define NT     (SPAN / TILE)     // 4 tiles per block
#define NRG    (N1 / 16)         // 128 rowgroups

// Scratch (allocation-free rule: __device__ globals)
__device__ float  g_kpTh[D * N2];          // 0.5*(k@Wk+bk)^T [d][m]
__device__ float4 g_qw4 [(N1 / 2) * D];    // (q_2p/2, q_2p+1/2, w/2, 0)
__device__ float  g_bias;                  // b + sum_d w_d/2
__device__ float  g_accP[SPLITS * N1 * D]; // partial PV accumulators
__device__ float  g_Ssum[SPLITS * N1];     // partial exp-sums
__device__ int    g_cnt [NRG];             // per-rowgroup completion counters

__device__ __forceinline__ float tanh_fast(float x) {
    float y;
    asm("tanh.approx.f32 %0, %1;" : "=f"(y) : "f"(x));
    return y;
}
__device__ __forceinline__ void cp_async16(void* saddr, const void* gptr) {
    uint32_t s = (uint32_t)__cvta_generic_to_shared(saddr);
    asm volatile("cp.async.cg.shared.global [%0], [%1], 16;" :: "r"(s), "l"(gptr));
}
__device__ __forceinline__ void cp_commit() { asm volatile("cp.async.commit_group;"); }
__device__ __forceinline__ void cp_wait0()  { asm volatile("cp.async.wait_group 0;" ::: "memory"); }

// ---------------------------------------------------------------------------
// Prep. Blocks 0..63   (job 0): row-pair x d-quad -> writes g_qw4 directly.
//       Blocks 64..191 (job 1): row x d-quad -> writes g_kpTh (transposed).
// Block 0 also zeroes combine counters; thread (0,0) computes g_bias.
// ---------------------------------------------------------------------------
__global__ void prep_kernel(const float* __restrict__ q,
                            const float* __restrict__ k,
                            const float* __restrict__ Wq, const float* __restrict__ bq,
                            const float* __restrict__ Wk, const float* __restrict__ bk,
                            const float* __restrict__ wvec,
                            const float* __restrict__ bptr) {
    const int tid = threadIdx.x;
    if (blockIdx.x < 64) {
        // job 0: q projection, pair-of-rows per thread
        if (blockIdx.x == 0 && tid < NRG) g_cnt[tid] = 0;
        if (blockIdx.x == 0 && tid == 0) {
            float s = bptr[0];
#pragma unroll
            for (int dd = 0; dd < D; dd++) s += 0.5f * wvec[dd];
            g_bias = s;
        }
        int i  = (blockIdx.x << 8) + tid;     // 0 .. 16383
        int p  = i >> 4;                      // row pair 0..1023
        int d0 = (i & 15) << 2;

        float4 r0a = make_float4(0.f, 0.f, 0.f, 0.f);
        float4 r1a = make_float4(0.f, 0.f, 0.f, 0.f);
#pragma unroll 16
        for (int kk = 0; kk < D; kk++) {
            float  x0 = q[(2 * p) * D + kk];
            float  x1 = q[(2 * p + 1) * D + kk];
            float4 w4 = *(const float4*)&Wq[kk * D + d0];
            r0a.x = fmaf(x0, w4.x, r0a.x);  r1a.x = fmaf(x1, w4.x, r1a.x);
            r0a.y = fmaf(x0, w4.y, r0a.y);  r1a.y = fmaf(x1, w4.y, r1a.y);
            r0a.z = fmaf(x0, w4.z, r0a.z);  r1a.z = fmaf(x1, w4.z, r1a.z);
            r0a.w = fmaf(x0, w4.w, r0a.w);  r1a.w = fmaf(x1, w4.w, r1a.w);
        }
        float4 b4 = *(const float4*)&bq[d0];
        float q0[4] = { 0.5f * (r0a.x + b4.x), 0.5f * (r0a.y + b4.y),
                        0.5f * (r0a.z + b4.z), 0.5f * (r0a.w + b4.w) };
        float q1[4] = { 0.5f * (r1a.x + b4.x), 0.5f * (r1a.y + b4.y),
                        0.5f * (r1a.z + b4.z), 0.5f * (r1a.w + b4.w) };
#pragma unroll
        for (int jj = 0; jj < 4; jj++) {
            int d = d0 + jj;
            g_qw4[p * D + d] = make_float4(q0[jj], q1[jj], 0.5f * wvec[d], 0.f);
        }
    } else {
        // job 1: k projection -> transposed halved
        int i  = ((blockIdx.x - 64) << 8) + tid;   // 0 .. 32767
        int n  = i >> 4;
        int d0 = (i & 15) << 2;

        float4 acc = make_float4(0.f, 0.f, 0.f, 0.f);
#pragma unroll 16
        for (int kk = 0; kk < D; kk++) {
            float  xs = k[n * D + kk];
            float4 w4 = *(const float4*)&Wk[kk * D + d0];
            acc.x = fmaf(xs, w4.x, acc.x);
            acc.y = fmaf(xs, w4.y, acc.y);
            acc.z = fmaf(xs, w4.z, acc.z);
            acc.w = fmaf(xs, w4.w, acc.w);
        }
        float4 b4 = *(const float4*)&bk[d0];
        g_kpTh[(d0 + 0) * N2 + n] = 0.5f * (acc.x + b4.x);
        g_kpTh[(d0 + 1) * N2 + n] = 0.5f * (acc.y + b4.y);
        g_kpTh[(d0 + 2) * N2 + n] = 0.5f * (acc.z + b4.z);
        g_kpTh[(d0 + 3) * N2 + n] = 0.5f * (acc.w + b4.w);
    }
}

// ---------------------------------------------------------------------------
// Main fused kernel. Grid = 1024: (rowgroup 0..127) x (split 0..7).
// Block 256 thr = 8 warps x 2 rows = 16 rows; block does SPAN=256 of N2.
// Software pipeline: PV(t-1) interleaved into score loop of tile t (3 of 4
// tiles run fused steady-state). k: 2-buffer ring, v: 3-buffer ring.
// Last-arriving block of each rowgroup combines the 8 partials inline.
// ---------------------------------------------------------------------------
__global__ __launch_bounds__(256, 2)
void attn_kernel(const float* __restrict__ vglob,    // [N2, D] original v
                 float* __restrict__ out,            // [N1, D]
                 float* __restrict__ att_score) {    // [N1, N2]
    extern __shared__ float sm[];
    float*  kb0 = sm;
    float*  kb1 = sm + 4096;
    float*  vbb = sm + 8192;               // 3 x 4096
    float4* qws = (float4*)(sm + 20480);   // [8 warps][64 d]
    float*  psm = sm + 22528;              // [8 warps][64 m][2 rows]

    const int tid   = threadIdx.x;
    const int warp  = tid >> 5;
    const int lane  = tid & 31;
    const int split = blockIdx.x & (SPLITS - 1);
    const int rg    = blockIdx.x >> 3;
    const int n0    = rg * 16;
    const int r0    = n0 + 2 * warp;
    const int r1    = r0 + 1;
    const int mbase = split * SPAN;

    // prologue: one cp.async group = qws table slice + tile 0 (k, v)
    {
        const float4* src = g_qw4 + rg * 512;
        cp_async16(qws + tid,       src + tid);
        cp_async16(qws + tid + 256, src + tid + 256);
        int r = tid >> 4, c = (tid & 15) << 2;
#pragma unroll
        for (int j = 0; j < 4; j++) {
            int rr = r + j * 16;
            cp_async16(kb0 + rr * 64 + c, g_kpTh + rr * N2 + mbase + c);
            cp_async16(vbb + rr * 64 + c, vglob + (mbase + rr) * D + c);
        }
        cp_commit();
    }
    const float bias = g_bias;

    float2 a0 = make_float2(0.f, 0.f);
    float2 a1 = make_float2(0.f, 0.f);
    float  S0 = 0.f, S1 = 0.f;

    float2* sr0 = (float2*)(att_score + (size_t)r0 * N2 + mbase);
    float2* sr1 = (float2*)(att_score + (size_t)r1 * N2 + mbase);
    float*  pw  = psm + warp * 128;

    for (int t = 0; t < NT; t++) {
        cp_wait0();
        __syncthreads();

        const float* kt = (t & 1) ? kb1 : kb0;

        if (t + 1 < NT) {
            float* kn = (t & 1) ? kb0 : kb1;
            float* vn = vbb + ((t + 1) % 3) * 4096;
            int r = tid >> 4, c = (tid & 15) << 2;
            int col0 = mbase + (t + 1) * 64;
#pragma unroll
            for (int j = 0; j < 4; j++) {
                int rr = r + j * 16;
                cp_async16(kn + rr * 64 + c, g_kpTh + rr * N2 + col0 + c);
                cp_async16(vn + rr * 64 + c, vglob + (col0 + rr) * D + c);
            }
            cp_commit();
        }

        float s00 = 0.f, s01 = 0.f, s10 = 0.f, s11 = 0.f;

        if (t == 0) {
            // scores only (no previous tile to accumulate)
#pragma unroll 8
            for (int d = 0; d < D; d++) {
                float4 qw = qws[warp * 64 + d];
                float2 kk = ((const float2*)(kt + d * 64))[lane];
                float t00 = tanh_fast(qw.x + kk.x);
                float t01 = tanh_fast(qw.x + kk.y);
                float t10 = tanh_fast(qw.y + kk.x);
                float t11 = tanh_fast(qw.y + kk.y);
                s00 = fmaf(qw.z, t00, s00);
                s01 = fmaf(qw.z, t01, s01);
                s10 = fmaf(qw.z, t10, s10);
                s11 = fmaf(qw.z, t11, s11);
            }
        } else {
            // fused: scores(t) + PV(t-1); MUFU binds, FMA/LDS hide under it
            const float* vprev = vbb + ((t - 1) % 3) * 4096;
#pragma unroll 8
            for (int d = 0; d < D; d++) {
                float4 qw = qws[warp * 64 + d];
                float2 kk = ((const float2*)(kt + d * 64))[lane];
                float t00 = tanh_fast(qw.x + kk.x);
                float t01 = tanh_fast(qw.x + kk.y);
                float t10 = tanh_fast(qw.y + kk.x);
                float t11 = tanh_fast(qw.y + kk.y);
                s00 = fmaf(qw.z, t00, s00);
                s01 = fmaf(qw.z, t01, s01);
                s10 = fmaf(qw.z, t10, s10);
                s11 = fmaf(qw.z, t11, s11);
                float2 pp = ((const float2*)pw)[d];             // broadcast
                float2 vv = ((const float2*)(vprev + d * 64))[lane];
                a0.x = fmaf(pp.x, vv.x, a0.x);
                a0.y = fmaf(pp.x, vv.y, a0.y);
                a1.x = fmaf(pp.y, vv.x, a1.x);
                a1.y = fmaf(pp.y, vv.y, a1.y);
            }
        }
        s00 += bias; s01 += bias; s10 += bias; s11 += bias;
        sr0[t * 32 + lane] = make_float2(s00, s01);
        sr1[t * 32 + lane] = make_float2(s10, s11);

        // softmax weights (scores bounded ~|3|: no running max)
        float p00 = __expf(s00), p01 = __expf(s01);
        float p10 = __expf(s10), p11 = __expf(s11);
        S0 += p00 + p01;
        S1 += p10 + p11;

        __syncwarp();
        ((float2*)pw)[2 * lane]     = make_float2(p00, p10);
        ((float2*)pw)[2 * lane + 1] = make_float2(p01, p11);
        __syncwarp();
    }

    // epilogue: PV for last tile
    {
        const float* vlast = vbb + ((NT - 1) % 3) * 4096;
#pragma unroll 8
        for (int m = 0; m < TILE; m++) {
            float2 pp = ((const float2*)pw)[m];
            float2 vv = ((const float2*)(vlast + m * 64))[lane];
            a0.x = fmaf(pp.x, vv.x, a0.x);
            a0.y = fmaf(pp.x, vv.y, a0.y);
            a1.x = fmaf(pp.y, vv.x, a1.x);
            a1.y = fmaf(pp.y, vv.y, a1.y);
        }
    }

    // S reduction over lanes (acc needs none: d-owned)
#pragma unroll
    for (int off = 16; off; off >>= 1) {
        S0 += __shfl_xor_sync(0xffffffffu, S0, off);
        S1 += __shfl_xor_sync(0xffffffffu, S1, off);
    }

    ((float2*)(g_accP + ((size_t)split * N1 + r0) * D))[lane] = a0;
    ((float2*)(g_accP + ((size_t)split * N1 + r1) * D))[lane] = a1;
    if (lane == 0) {
        g_Ssum[split * N1 + r0] = S0;
        g_Ssum[split * N1 + r1] = S1;
    }

    // ---- inline combine: last-arriving block of this rowgroup ----
    __threadfence();
    __shared__ int is_last;
    if (tid == 0) {
        int old = atomicAdd(&g_cnt[rg], 1);
        is_last = (old == SPLITS - 1);
    }
    __syncthreads();
    if (is_last) {
        // 256 threads = 16 rows x 16 d-quads
        int n  = n0 + (tid >> 4);
        int d0 = (tid & 15) << 2;
        float4 a = make_float4(0.f, 0.f, 0.f, 0.f);
        float  S = 0.f;
#pragma unroll
        for (int s = 0; s < SPLITS; s++) {
            float4 p = __ldcg((const float4*)&g_accP[((size_t)s * N1 + n) * D + d0]);
            a.x += p.x; a.y += p.y; a.z += p.z; a.w += p.w;
            S += __ldcg(&g_Ssum[s * N1 + n]);
        }
        float r = __fdividef(1.f, S);
        *(float4*)&out[(size_t)n * D + d0] =
            make_float4(a.x * r, a.y * r, a.z * r, a.w * r);
    }
}

// ---------------------------------------------------------------------------
extern "C" void kernel_launch(void* const* d_in, const int* in_sizes, int n_in,
                              void* d_out, int out_size) {
    const float* q  = (const float*)d_in[0];
    const float* k  = (const float*)d_in[1];
    const float* v  = (const float*)d_in[2];
    const float* Wq = (const float*)d_in[3];
    const float* bq = (const float*)d_in[4];
    const float* Wk = (const float*)d_in[5];
    const float* bk = (const float*)d_in[6];
    const float* w  = (const float*)d_in[7];
    const float* b  = (const float*)d_in[8];

    float* out       = (float*)d_out;          // [N1, D] first
    float* att_score = out + N1 * D;           // then [N1, N2]

    const int SMEM_BYTES = (5 * 4096 + 2048 + 1024) * (int)sizeof(float);   // 94208
    cudaFuncSetAttribute(attn_kernel, cudaFuncAttributeMaxDynamicSharedMemorySize,
                         SMEM_BYTES);

    prep_kernel<<<192, 256>>>(q, k, Wq, bq, Wk, bk, w, b);
    attn_kernel<<<NRG * SPLITS, 256, SMEM_BYTES>>>(v, out, att_score);
}

// round 16
// speedup vs baseline: 1.1727x; 1.0727x over previous
#include <cuda_runtime.h>
#include <cstdint>

#define N1     2048
#define N2     2048
#define D      64
#define TILE   64
#define SPLITS 8
#define SPAN   (N2 / SPLITS)     // 256 m per block
#define NT     (SPAN / TILE)     // 4 tiles per block
#define NRG    (N1 / 16)         // 128 rowgroups

// Scratch (allocation-free rule: __device__ globals)
__device__ float  g_kpTh[D * N2];          // 0.5*(k@Wk+bk)^T [d][m]
__device__ float4 g_qw4 [(N1 / 2) * D];    // (q_2p/2, q_2p+1/2, w/2, 0)
__device__ float  g_bias;                  // b + sum_d w_d/2
__device__ float  g_accP[SPLITS * N1 * D]; // partial PV accumulators
__device__ float  g_Ssum[SPLITS * N1];     // partial exp-sums

__device__ __forceinline__ float tanh_fast(float x) {
    float y;
    asm("tanh.approx.f32 %0, %1;" : "=f"(y) : "f"(x));
    return y;
}
__device__ __forceinline__ void cp_async16(void* saddr, const void* gptr) {
    uint32_t s = (uint32_t)__cvta_generic_to_shared(saddr);
    asm volatile("cp.async.cg.shared.global [%0], [%1], 16;" :: "r"(s), "l"(gptr));
}
__device__ __forceinline__ void cp_commit() { asm volatile("cp.async.commit_group;"); }
__device__ __forceinline__ void cp_wait0()  { asm volatile("cp.async.wait_group 0;" ::: "memory"); }

// ---------------------------------------------------------------------------
// Prep. Blocks 0..63   (job 0): row-pair x d-quad -> writes g_qw4 directly.
//       Blocks 64..191 (job 1): row x d-quad -> writes g_kpTh (transposed).
// Thread (0,0) computes g_bias.
// ---------------------------------------------------------------------------
__global__ void prep_kernel(const float* __restrict__ q,
                            const float* __restrict__ k,
                            const float* __restrict__ Wq, const float* __restrict__ bq,
                            const float* __restrict__ Wk, const float* __restrict__ bk,
                            const float* __restrict__ wvec,
                            const float* __restrict__ bptr) {
    const int tid = threadIdx.x;
    if (blockIdx.x < 64) {
        // job 0: q projection, pair-of-rows per thread
        if (blockIdx.x == 0 && tid == 0) {
            float s = bptr[0];
#pragma unroll
            for (int dd = 0; dd < D; dd++) s += 0.5f * wvec[dd];
            g_bias = s;
        }
        int i  = (blockIdx.x << 8) + tid;     // 0 .. 16383
        int p  = i >> 4;                      // row pair 0..1023
        int d0 = (i & 15) << 2;

        float4 r0a = make_float4(0.f, 0.f, 0.f, 0.f);
        float4 r1a = make_float4(0.f, 0.f, 0.f, 0.f);
#pragma unroll 16
        for (int kk = 0; kk < D; kk++) {
            float  x0 = q[(2 * p) * D + kk];
            float  x1 = q[(2 * p + 1) * D + kk];
            float4 w4 = *(const float4*)&Wq[kk * D + d0];
            r0a.x = fmaf(x0, w4.x, r0a.x);  r1a.x = fmaf(x1, w4.x, r1a.x);
            r0a.y = fmaf(x0, w4.y, r0a.y);  r1a.y = fmaf(x1, w4.y, r1a.y);
            r0a.z = fmaf(x0, w4.z, r0a.z);  r1a.z = fmaf(x1, w4.z, r1a.z);
            r0a.w = fmaf(x0, w4.w, r0a.w);  r1a.w = fmaf(x1, w4.w, r1a.w);
        }
        float4 b4 = *(const float4*)&bq[d0];
        float q0[4] = { 0.5f * (r0a.x + b4.x), 0.5f * (r0a.y + b4.y),
                        0.5f * (r0a.z + b4.z), 0.5f * (r0a.w + b4.w) };
        float q1[4] = { 0.5f * (r1a.x + b4.x), 0.5f * (r1a.y + b4.y),
                        0.5f * (r1a.z + b4.z), 0.5f * (r1a.w + b4.w) };
#pragma unroll
        for (int jj = 0; jj < 4; jj++) {
            int d = d0 + jj;
            g_qw4[p * D + d] = make_float4(q0[jj], q1[jj], 0.5f * wvec[d], 0.f);
        }
    } else {
        // job 1: k projection -> transposed halved
        int i  = ((blockIdx.x - 64) << 8) + tid;   // 0 .. 32767
        int n  = i >> 4;
        int d0 = (i & 15) << 2;

        float4 acc = make_float4(0.f, 0.f, 0.f, 0.f);
#pragma unroll 16
        for (int kk = 0; kk < D; kk++) {
            float  xs = k[n * D + kk];
            float4 w4 = *(const float4*)&Wk[kk * D + d0];
            acc.x = fmaf(xs, w4.x, acc.x);
            acc.y = fmaf(xs, w4.y, acc.y);
            acc.z = fmaf(xs, w4.z, acc.z);
            acc.w = fmaf(xs, w4.w, acc.w);
        }
        float4 b4 = *(const float4*)&bk[d0];
        g_kpTh[(d0 + 0) * N2 + n] = 0.5f * (acc.x + b4.x);
        g_kpTh[(d0 + 1) * N2 + n] = 0.5f * (acc.y + b4.y);
        g_kpTh[(d0 + 2) * N2 + n] = 0.5f * (acc.z + b4.z);
        g_kpTh[(d0 + 3) * N2 + n] = 0.5f * (acc.w + b4.w);
    }
}

// ---------------------------------------------------------------------------
// Main fused kernel. Grid = 1024: (rowgroup 0..127) x (split 0..7).
// Block 256 thr = 8 warps x 2 rows = 16 rows; block does SPAN=256 of N2.
// Software pipeline: PV(t-1) interleaved into score loop of tile t (3 of 4
// tiles run fused steady-state). k: 2-buffer ring, v: 3-buffer ring.
// No fences/atomics in the critical path — combine is a separate kernel.
// ---------------------------------------------------------------------------
__global__ __launch_bounds__(256, 2)
void attn_kernel(const float* __restrict__ vglob,    // [N2, D] original v
                 float* __restrict__ att_score) {    // [N1, N2]
    extern __shared__ float sm[];
    float*  kb0 = sm;
    float*  kb1 = sm + 4096;
    float*  vbb = sm + 8192;               // 3 x 4096
    float4* qws = (float4*)(sm + 20480);   // [8 warps][64 d]
    float*  psm = sm + 22528;              // [8 warps][64 m][2 rows]

    const int tid   = threadIdx.x;
    const int warp  = tid >> 5;
    const int lane  = tid & 31;
    const int split = blockIdx.x & (SPLITS - 1);
    const int rg    = blockIdx.x >> 3;
    const int n0    = rg * 16;
    const int r0    = n0 + 2 * warp;
    const int r1    = r0 + 1;
    const int mbase = split * SPAN;

    // prologue: one cp.async group = qws table slice + tile 0 (k, v)
    {
        const float4* src = g_qw4 + rg * 512;
        cp_async16(qws + tid,       src + tid);
        cp_async16(qws + tid + 256, src + tid + 256);
        int r = tid >> 4, c = (tid & 15) << 2;
#pragma unroll
        for (int j = 0; j < 4; j++) {
            int rr = r + j * 16;
            cp_async16(kb0 + rr * 64 + c, g_kpTh + rr * N2 + mbase + c);
            cp_async16(vbb + rr * 64 + c, vglob + (mbase + rr) * D + c);
        }
        cp_commit();
    }
    const float bias = g_bias;

    float2 a0 = make_float2(0.f, 0.f);
    float2 a1 = make_float2(0.f, 0.f);
    float  S0 = 0.f, S1 = 0.f;

    float2* sr0 = (float2*)(att_score + (size_t)r0 * N2 + mbase);
    float2* sr1 = (float2*)(att_score + (size_t)r1 * N2 + mbase);
    float*  pw  = psm + warp * 128;

    for (int t = 0; t < NT; t++) {
        cp_wait0();
        __syncthreads();

        const float* kt = (t & 1) ? kb1 : kb0;

        if (t + 1 < NT) {
            float* kn = (t & 1) ? kb0 : kb1;
            float* vn = vbb + ((t + 1) % 3) * 4096;
            int r = tid >> 4, c = (tid & 15) << 2;
            int col0 = mbase + (t + 1) * 64;
#pragma unroll
            for (int j = 0; j < 4; j++) {
                int rr = r + j * 16;
                cp_async16(kn + rr * 64 + c, g_kpTh + rr * N2 + col0 + c);
                cp_async16(vn + rr * 64 + c, vglob + (col0 + rr) * D + c);
            }
            cp_commit();
        }

        float s00 = 0.f, s01 = 0.f, s10 = 0.f, s11 = 0.f;

        if (t == 0) {
            // scores only (no previous tile to accumulate)
#pragma unroll 8
            for (int d = 0; d < D; d++) {
                float4 qw = qws[warp * 64 + d];
                float2 kk = ((const float2*)(kt + d * 64))[lane];
                float t00 = tanh_fast(qw.x + kk.x);
                float t01 = tanh_fast(qw.x + kk.y);
                float t10 = tanh_fast(qw.y + kk.x);
                float t11 = tanh_fast(qw.y + kk.y);
                s00 = fmaf(qw.z, t00, s00);
                s01 = fmaf(qw.z, t01, s01);
                s10 = fmaf(qw.z, t10, s10);
                s11 = fmaf(qw.z, t11, s11);
            }
        } else {
            // fused: scores(t) + PV(t-1); MUFU binds, FMA/LDS hide under it
            const float* vprev = vbb + ((t - 1) % 3) * 4096;
#pragma unroll 8
            for (int d = 0; d < D; d++) {
                float4 qw = qws[warp * 64 + d];
                float2 kk = ((const float2*)(kt + d * 64))[lane];
                float t00 = tanh_fast(qw.x + kk.x);
                float t01 = tanh_fast(qw.x + kk.y);
                float t10 = tanh_fast(qw.y + kk.x);
                float t11 = tanh_fast(qw.y + kk.y);
                s00 = fmaf(qw.z, t00, s00);
                s01 = fmaf(qw.z, t01, s01);
                s10 = fmaf(qw.z, t10, s10);
                s11 = fmaf(qw.z, t11, s11);
                float2 pp = ((const float2*)pw)[d];             // broadcast
                float2 vv = ((const float2*)(vprev + d * 64))[lane];
                a0.x = fmaf(pp.x, vv.x, a0.x);
                a0.y = fmaf(pp.x, vv.y, a0.y);
                a1.x = fmaf(pp.y, vv.x, a1.x);
                a1.y = fmaf(pp.y, vv.y, a1.y);
            }
        }
        s00 += bias; s01 += bias; s10 += bias; s11 += bias;
        sr0[t * 32 + lane] = make_float2(s00, s01);
        sr1[t * 32 + lane] = make_float2(s10, s11);

        // softmax weights (scores bounded ~|3|: no running max)
        float p00 = __expf(s00), p01 = __expf(s01);
        float p10 = __expf(s10), p11 = __expf(s11);
        S0 += p00 + p01;
        S1 += p10 + p11;

        __syncwarp();
        ((float2*)pw)[2 * lane]     = make_float2(p00, p10);
        ((float2*)pw)[2 * lane + 1] = make_float2(p01, p11);
        __syncwarp();
    }

    // epilogue: PV for last tile
    {
        const float* vlast = vbb + ((NT - 1) % 3) * 4096;
#pragma unroll 8
        for (int m = 0; m < TILE; m++) {
            float2 pp = ((const float2*)pw)[m];
            float2 vv = ((const float2*)(vlast + m * 64))[lane];
            a0.x = fmaf(pp.x, vv.x, a0.x);
            a0.y = fmaf(pp.x, vv.y, a0.y);
            a1.x = fmaf(pp.y, vv.x, a1.x);
            a1.y = fmaf(pp.y, vv.y, a1.y);
        }
    }

    // S reduction over lanes (acc needs none: d-owned)
#pragma unroll
    for (int off = 16; off; off >>= 1) {
        S0 += __shfl_xor_sync(0xffffffffu, S0, off);
        S1 += __shfl_xor_sync(0xffffffffu, S1, off);
    }

    ((float2*)(g_accP + ((size_t)split * N1 + r0) * D))[lane] = a0;
    ((float2*)(g_accP + ((size_t)split * N1 + r1) * D))[lane] = a1;
    if (lane == 0) {
        g_Ssum[split * N1 + r0] = S0;
        g_Ssum[split * N1 + r1] = S1;
    }
}

// ---------------------------------------------------------------------------
// Combine splits: thread owns a d-quad; 8 independent LDG.128 (L2-hot).
// 256 blocks x 128 threads = exactly N1*16 threads.
// ---------------------------------------------------------------------------
__global__ void combine_kernel(float* __restrict__ out) {
    int i  = blockIdx.x * 128 + threadIdx.x;   // 0 .. 32767
    int n  = i >> 4;
    int d0 = (i & 15) << 2;
    float4 a = make_float4(0.f, 0.f, 0.f, 0.f);
    float  S = 0.f;
#pragma unroll
    for (int s = 0; s < SPLITS; s++) {
        float4 p = *(const float4*)&g_accP[((size_t)s * N1 + n) * D + d0];
        a.x += p.x; a.y += p.y; a.z += p.z; a.w += p.w;
        S += g_Ssum[s * N1 + n];
    }
    float r = __fdividef(1.f, S);
    *(float4*)&out[(size_t)n * D + d0] = make_float4(a.x * r, a.y * r, a.z * r, a.w * r);
}

// ---------------------------------------------------------------------------
extern "C" void kernel_launch(void* const* d_in, const int* in_sizes, int n_in,
                              void* d_out, int out_size) {
    const float* q  = (const float*)d_in[0];
    const float* k  = (const float*)d_in[1];
    const float* v  = (const float*)d_in[2];
    const float* Wq = (const float*)d_in[3];
    const float* bq = (const float*)d_in[4];
    const float* Wk = (const float*)d_in[5];
    const float* bk = (const float*)d_in[6];
    const float* w  = (const float*)d_in[7];
    const float* b  = (const float*)d_in[8];

    float* out       = (float*)d_out;          // [N1, D] first
    float* att_score = out + N1 * D;           // then [N1, N2]

    const int SMEM_BYTES = (5 * 4096 + 2048 + 1024) * (int)sizeof(float);   // 94208
    cudaFuncSetAttribute(attn_kernel, cudaFuncAttributeMaxDynamicSharedMemorySize,
                         SMEM_BYTES);

    prep_kernel<<<192, 256>>>(q, k, Wq, bq, Wk, bk, w, b);
    attn_kernel<<<NRG * SPLITS, 256, SMEM_BYTES>>>(v, att_score);
    combine_kernel<<<256, 128>>>(out);
}